// round 15
// baseline (speedup 1.0000x reference)
#include <cuda_runtime.h>
#include <cuda_bf16.h>
#include <cstdint>

#define C 128
#define WSTR 136
#define WPL (64 * WSTR)
#define CW 8                 // compute warps
#define THREADS 288          // 8 compute + 1 producer warp
#define EPSF 1e-8f

__device__ float g_Mm[C * C];
__device__ float g_Md[C * C];
// bake order: 0 Wgcn, 1 Mm, 2 Wvm, 3 Md, 4 Wvd, 5 W1
__device__ __align__(16) uint32_t g_BH[6][WPL];
__device__ __align__(16) uint32_t g_BL[6][WPL];

// ---- smem u32 layout ----
// [0..7]: mbarriers fullA(0), fullB(2), freeA(4), freeB(6) (b64 each)
#define U_WA 16
#define U_WB (U_WA + 2 * WPL)
#define U_X1 (U_WB + 2 * WPL)          // per-warp scratch: 64 idx x 32 lanes
#define U_TOT (U_X1 + CW * 2048)       // 51216 u32 = 204,864 B

__device__ __forceinline__ uint32_t s2u(const void* p) {
    uint32_t a;
    asm("{ .reg .u64 t; cvta.to.shared.u64 t, %1; cvt.u32.u64 %0, t; }" : "=r"(a) : "l"(p));
    return a;
}
#define MBAR_INIT(a, c) asm volatile("mbarrier.init.shared.b64 [%0], %1;" ::"r"(a), "r"(c) : "memory")
#define MBAR_EXPECT(a, b) \
    asm volatile("mbarrier.arrive.expect_tx.shared.b64 _, [%0], %1;" ::"r"(a), "r"(b) : "memory")
#define MBAR_ARRIVE(a) \
    asm volatile("mbarrier.arrive.shared.b64 _, [%0];" ::"r"(a) : "memory")
__device__ __forceinline__ void mbar_wait(uint32_t a, uint32_t par) {
    asm volatile(
        "{\n\t.reg .pred P;\n\tWL_%=:\n\t"
        "mbarrier.try_wait.parity.acquire.cta.shared::cta.b64 P, [%0], %1, 0x989680;\n\t"
        "@P bra.uni WD_%=;\n\tbra.uni WL_%=;\n\tWD_%=:\n\t}" ::"r"(a), "r"(par) : "memory");
}
__device__ __forceinline__ void bulk_g2s(uint32_t dst, const void* gsrc, uint32_t bytes,
                                         uint32_t mbar) {
    asm volatile(
        "{ .reg .u64 g; cvta.to.global.u64 g, %1;\n\t"
        "cp.async.bulk.shared::cluster.global.mbarrier::complete_tx::bytes [%0], [g], %2, [%3]; }"
        ::"r"(dst), "l"(gsrc), "r"(bytes), "r"(mbar) : "memory");
}

__device__ __forceinline__ void split_pack(float x0, float x1, uint32_t& h, uint32_t& l) {
    uint32_t u0 = __float_as_uint(x0), u1 = __float_as_uint(x1);
    h = __byte_perm(u0, u1, 0x7632);
    float l0 = x0 - __uint_as_float(u0 & 0xFFFF0000u);
    float l1 = x1 - __uint_as_float(u1 & 0xFFFF0000u);
    __nv_bfloat162 t = __floats2bfloat162_rn(l0, l1);
    l = *(uint32_t*)&t;
}
__device__ __forceinline__ float2 unpack2u(uint32_t h, uint32_t l) {
    float2 a = __bfloat1622float2(*(__nv_bfloat162*)&h);
    float2 b = __bfloat1622float2(*(__nv_bfloat162*)&l);
    return make_float2(a.x + b.x, a.y + b.y);
}
__device__ __forceinline__ void mma16816(float* d, const uint32_t* a, uint32_t b0, uint32_t b1) {
    asm volatile(
        "mma.sync.aligned.m16n8k16.row.col.f32.bf16.bf16.f32 "
        "{%0,%1,%2,%3}, {%4,%5,%6,%7}, {%8,%9}, {%0,%1,%2,%3};"
        : "+f"(d[0]), "+f"(d[1]), "+f"(d[2]), "+f"(d[3])
        : "r"(a[0]), "r"(a[1]), "r"(a[2]), "r"(a[3]), "r"(b0), "r"(b1));
}
#define MMA3(accn, ah, al, bh0, bh1, bl0, bl1) \
    do {                                       \
        mma16816(accn, ah, bh0, bh1);          \
        mma16816(accn, al, bh0, bh1);          \
        mma16816(accn, ah, bl0, bl1);          \
    } while (0)

// GEMM, A fragments in registers (xh/xl[32], layout idx=4*k0+i), full 128 cols.
__device__ __forceinline__ void gemm_regA(const uint32_t* xh, const uint32_t* xl,
                                          const uint32_t* W, float acc[16][4], int g, int t) {
    const uint32_t* pb = W + t * WSTR + g * 4;
#pragma unroll
    for (int k0 = 0; k0 < 8; k0++) {
        const uint32_t* ah = xh + 4 * k0;
        const uint32_t* al = xl + 4 * k0;
#pragma unroll
        for (int c32 = 0; c32 < 4; c32++) {
            uint4 bh0 = *(const uint4*)(pb + c32 * 32);
            uint4 bh1 = *(const uint4*)(pb + c32 * 32 + 4 * WSTR);
            uint4 bl0 = *(const uint4*)(pb + c32 * 32 + WPL);
            uint4 bl1 = *(const uint4*)(pb + c32 * 32 + WPL + 4 * WSTR);
            MMA3(acc[4 * c32 + 0], ah, al, bh0.x, bh1.x, bl0.x, bl1.x);
            MMA3(acc[4 * c32 + 1], ah, al, bh0.y, bh1.y, bl0.y, bl1.y);
            MMA3(acc[4 * c32 + 2], ah, al, bh0.z, bh1.z, bl0.z, bl1.z);
            MMA3(acc[4 * c32 + 3], ah, al, bh0.w, bh1.w, bl0.w, bl1.w);
        }
        pb += 8 * WSTR;
    }
}
// GEMM, A fragments from per-warp smem scratch (scr already +lane; idx*32 stride)
__device__ __forceinline__ void gemm_smemA(const uint32_t* scr, const uint32_t* W,
                                           float acc[16][4], int g, int t) {
    const uint32_t* pb = W + t * WSTR + g * 4;
#pragma unroll 2
    for (int k0 = 0; k0 < 8; k0++) {
        uint32_t ah[4], al[4];
#pragma unroll
        for (int i = 0; i < 4; i++) {
            ah[i] = scr[(4 * k0 + i) * 32];
            al[i] = scr[(32 + 4 * k0 + i) * 32];
        }
#pragma unroll
        for (int c32 = 0; c32 < 4; c32++) {
            uint4 bh0 = *(const uint4*)(pb + c32 * 32);
            uint4 bh1 = *(const uint4*)(pb + c32 * 32 + 4 * WSTR);
            uint4 bl0 = *(const uint4*)(pb + c32 * 32 + WPL);
            uint4 bl1 = *(const uint4*)(pb + c32 * 32 + WPL + 4 * WSTR);
            MMA3(acc[4 * c32 + 0], ah, al, bh0.x, bh1.x, bl0.x, bl1.x);
            MMA3(acc[4 * c32 + 1], ah, al, bh0.y, bh1.y, bl0.y, bl1.y);
            MMA3(acc[4 * c32 + 2], ah, al, bh0.z, bh1.z, bl0.z, bl1.z);
            MMA3(acc[4 * c32 + 3], ah, al, bh0.w, bh1.w, bl0.w, bl1.w);
        }
        pb += 8 * WSTR;
    }
}

// ---------------- prep ----------------
__global__ void precompute_M_kernel(const float* __restrict__ Wq_m, const float* __restrict__ Wk_m,
                                    const float* __restrict__ Wq_d, const float* __restrict__ Wk_d) {
    const float* Wq = blockIdx.y ? Wq_d : Wq_m;
    const float* Wk = blockIdx.y ? Wk_d : Wk_m;
    float* M = blockIdx.y ? g_Md : g_Mm;
    int i = blockIdx.x, t = threadIdx.x;
    __shared__ float qrow[C];
    qrow[t] = Wq[i * C + t];
    __syncthreads();
    const float* wkr = Wk + t * C;
    float a0 = 0.f, a1 = 0.f, a2 = 0.f, a3 = 0.f;
#pragma unroll 8
    for (int j = 0; j < C; j += 4) {
        a0 += qrow[j] * wkr[j];
        a1 += qrow[j + 1] * wkr[j + 1];
        a2 += qrow[j + 2] * wkr[j + 2];
        a3 += qrow[j + 3] * wkr[j + 3];
    }
    M[i * C + t] = ((a0 + a1) + (a2 + a3)) * 0.08838834764831845f;
}

__global__ void bake_kernel(const float* __restrict__ Wg, const float* __restrict__ Wvm,
                            const float* __restrict__ Wvd, const float* __restrict__ W1) {
    int w = blockIdx.y;
    const float* src = (w == 0) ? Wg : (w == 1) ? g_Mm : (w == 2) ? Wvm
                      : (w == 3) ? g_Md : (w == 4) ? Wvd : W1;
    int idx = blockIdx.x * blockDim.x + threadIdx.x;  // 0..8191
    int nt = idx & 3, g = (idx >> 2) & 7, c32 = (idx >> 5) & 3, k2 = idx >> 7;
    int n = c32 * 32 + nt * 8 + g;
    uint32_t h, l;
    split_pack(src[(2 * k2) * C + n], src[(2 * k2 + 1) * C + n], h, l);
    g_BH[w][k2 * WSTR + (idx & 127)] = h;
    g_BL[w][k2 * WSTR + (idx & 127)] = l;
}

// ---------------- fused: warp-decoupled, 8 warps x 16 rows ----------------
__global__ void __launch_bounds__(THREADS, 1)
fused_kernel(const float* __restrict__ em, const float* __restrict__ ed,
             const float* __restrict__ W2, float* __restrict__ out) {
    extern __shared__ uint32_t sm[];
    const uint32_t sb = s2u(sm);
    const uint32_t fullA = sb + 0, fullB = sb + 8, freeA = sb + 16, freeB = sb + 24;
    uint32_t* WA = sm + U_WA;
    uint32_t* WB = sm + U_WB;

    const int tid = threadIdx.x;
    const int w = tid >> 5, lane = tid & 31;
    const int g = lane >> 2, t = lane & 3;

    if (tid == 256) {  // producer init + first two copies
        MBAR_INIT(fullA, 1);
        MBAR_INIT(fullB, 1);
        MBAR_INIT(freeA, CW);
        MBAR_INIT(freeB, CW);
        MBAR_EXPECT(fullA, 2u * WPL * 4);
        bulk_g2s(sb + U_WA * 4, &g_BH[0][0], WPL * 4, fullA);              // Wgcn
        bulk_g2s(sb + (U_WA + WPL) * 4, &g_BL[0][0], WPL * 4, fullA);
        MBAR_EXPECT(fullB, 2u * WPL * 4);
        bulk_g2s(sb + U_WB * 4, &g_BH[1][0], WPL * 4, fullB);              // Mm
        bulk_g2s(sb + (U_WB + WPL) * 4, &g_BL[1][0], WPL * 4, fullB);
    }
    __syncthreads();

    if (w == CW) {  // ---- producer warp ----
        if (lane == 0) {
            auto cp = [&](uint32_t mbar, uint32_t slot, int wi) {
                MBAR_EXPECT(mbar, 2u * WPL * 4);
                bulk_g2s(sb + slot * 4, &g_BH[wi][0], WPL * 4, mbar);
                bulk_g2s(sb + (slot + WPL) * 4, &g_BL[wi][0], WPL * 4, mbar);
            };
            mbar_wait(freeA, 0); cp(fullA, U_WA, 3);  // Md
            mbar_wait(freeB, 0); cp(fullB, U_WB, 2);  // Wvm
            mbar_wait(freeA, 1); cp(fullA, U_WA, 4);  // Wvd
            mbar_wait(freeB, 1); cp(fullB, U_WB, 5);  // W1
        }
        return;
    }

    // ---- compute warp: owns rows wrow..wrow+15; lane handles rows g, g+8 ----
    const long base = (long)blockIdx.x * 128;
    const long row1 = base + w * 16 + g, row2 = row1 + 8;
    const float* pe1 = em + row1 * C;
    const float* pe2 = em + row2 * C;
    const float* pd1 = ed + row1 * C;
    const float* pd2 = ed + row2 * C;
    uint32_t* scr = sm + U_X1 + w * 2048 + lane;  // idx*32 stride

    uint32_t xh[32], xl[32];  // register-chained A fragments (idx = 2*nt + rr)

    // ================= GCN (Wgcn in A) + adjacency =================
    float acc0[16][4] = {}, acc1[16][4] = {};
    float sa1 = 0, q01 = 0, q11 = 0, dp1 = 0, sa2 = 0, q02 = 0, q12 = 0, dp2 = 0;
    mbar_wait(fullA, 0);
    {
        const uint32_t* pb = WA + t * WSTR + g * 4;
#pragma unroll
        for (int k0 = 0; k0 < 8; k0++) {
            float2 e1a = *(const float2*)(pe1 + 16 * k0 + 2 * t);
            float2 e1b = *(const float2*)(pe1 + 16 * k0 + 8 + 2 * t);
            float2 e2a = *(const float2*)(pe2 + 16 * k0 + 2 * t);
            float2 e2b = *(const float2*)(pe2 + 16 * k0 + 8 + 2 * t);
            float2 d1a = *(const float2*)(pd1 + 16 * k0 + 2 * t);
            float2 d1b = *(const float2*)(pd1 + 16 * k0 + 8 + 2 * t);
            float2 d2a = *(const float2*)(pd2 + 16 * k0 + 2 * t);
            float2 d2b = *(const float2*)(pd2 + 16 * k0 + 8 + 2 * t);
            sa1 += fabsf(e1a.x - d1a.x) + fabsf(e1a.y - d1a.y) + fabsf(e1b.x - d1b.x) +
                   fabsf(e1b.y - d1b.y);
            q01 += e1a.x * e1a.x + e1a.y * e1a.y + e1b.x * e1b.x + e1b.y * e1b.y;
            q11 += d1a.x * d1a.x + d1a.y * d1a.y + d1b.x * d1b.x + d1b.y * d1b.y;
            dp1 += e1a.x * d1a.x + e1a.y * d1a.y + e1b.x * d1b.x + e1b.y * d1b.y;
            sa2 += fabsf(e2a.x - d2a.x) + fabsf(e2a.y - d2a.y) + fabsf(e2b.x - d2b.x) +
                   fabsf(e2b.y - d2b.y);
            q02 += e2a.x * e2a.x + e2a.y * e2a.y + e2b.x * e2b.x + e2b.y * e2b.y;
            q12 += d2a.x * d2a.x + d2a.y * d2a.y + d2b.x * d2b.x + d2b.y * d2b.y;
            dp2 += e2a.x * d2a.x + e2a.y * d2a.y + e2b.x * d2b.x + e2b.y * d2b.y;
            uint32_t ah[4], al[4], ch[4], cl[4];
            split_pack(e1a.x, e1a.y, ah[0], al[0]);
            split_pack(e2a.x, e2a.y, ah[1], al[1]);
            split_pack(e1b.x, e1b.y, ah[2], al[2]);
            split_pack(e2b.x, e2b.y, ah[3], al[3]);
            split_pack(d1a.x, d1a.y, ch[0], cl[0]);
            split_pack(d2a.x, d2a.y, ch[1], cl[1]);
            split_pack(d1b.x, d1b.y, ch[2], cl[2]);
            split_pack(d2b.x, d2b.y, ch[3], cl[3]);
#pragma unroll
            for (int c32 = 0; c32 < 4; c32++) {
                uint4 bh0 = *(const uint4*)(pb + c32 * 32);
                uint4 bh1 = *(const uint4*)(pb + c32 * 32 + 4 * WSTR);
                uint4 bl0 = *(const uint4*)(pb + c32 * 32 + WPL);
                uint4 bl1 = *(const uint4*)(pb + c32 * 32 + WPL + 4 * WSTR);
                MMA3(acc0[4 * c32 + 0], ah, al, bh0.x, bh1.x, bl0.x, bl1.x);
                MMA3(acc0[4 * c32 + 1], ah, al, bh0.y, bh1.y, bl0.y, bl1.y);
                MMA3(acc0[4 * c32 + 2], ah, al, bh0.z, bh1.z, bl0.z, bl1.z);
                MMA3(acc0[4 * c32 + 3], ah, al, bh0.w, bh1.w, bl0.w, bl1.w);
                MMA3(acc1[4 * c32 + 0], ch, cl, bh0.x, bh1.x, bl0.x, bl1.x);
                MMA3(acc1[4 * c32 + 1], ch, cl, bh0.y, bh1.y, bl0.y, bl1.y);
                MMA3(acc1[4 * c32 + 2], ch, cl, bh0.z, bh1.z, bl0.z, bl1.z);
                MMA3(acc1[4 * c32 + 3], ch, cl, bh0.w, bh1.w, bl0.w, bl1.w);
            }
            pb += 8 * WSTR;
        }
    }
    if (lane == 0) MBAR_ARRIVE(freeA);
#pragma unroll
    for (int o = 1; o < 4; o <<= 1) {
        sa1 += __shfl_xor_sync(~0u, sa1, o); q01 += __shfl_xor_sync(~0u, q01, o);
        q11 += __shfl_xor_sync(~0u, q11, o); dp1 += __shfl_xor_sync(~0u, dp1, o);
        sa2 += __shfl_xor_sync(~0u, sa2, o); q02 += __shfl_xor_sync(~0u, q02, o);
        q12 += __shfl_xor_sync(~0u, q12, o); dp2 += __shfl_xor_sync(~0u, dp2, o);
    }
    float a1v, b1v, a2v, b2v;
    {
        float cos1 = dp1 / (sqrtf(q01 + EPSF) * sqrtf(q11 + EPSF));
        float cp1 = cos1 > 0.f ? cos1 : 0.01f * cos1;
        a1v = fminf(1.f / (1.f + cp1), 1.f / (1.f + sa1));
        b1v = fminf(cp1 / (1.f + cp1), sa1 / (1.f + sa1));
        float cos2 = dp2 / (sqrtf(q02 + EPSF) * sqrtf(q12 + EPSF));
        float cp2 = cos2 > 0.f ? cos2 : 0.01f * cos2;
        a2v = fminf(1.f / (1.f + cp2), 1.f / (1.f + sa2));
        b2v = fminf(cp2 / (1.f + cp2), sa2 / (1.f + sa2));
    }
    // GCN epilogue: x0 -> regs, x1 -> scratch
#pragma unroll
    for (int nt = 0; nt < 16; nt++) {
        int cc = 8 * nt + 2 * t;
        float2 e1 = *(const float2*)(pe1 + cc), e2 = *(const float2*)(pe2 + cc);
        float2 d1 = *(const float2*)(pd1 + cc), d2 = *(const float2*)(pd2 + cc);
        split_pack(fmaxf(a1v * acc0[nt][0] + b1v * acc1[nt][0], 0.f) + e1.x,
                   fmaxf(a1v * acc0[nt][1] + b1v * acc1[nt][1], 0.f) + e1.y,
                   xh[2 * nt], xl[2 * nt]);
        split_pack(fmaxf(a2v * acc0[nt][2] + b2v * acc1[nt][2], 0.f) + e2.x,
                   fmaxf(a2v * acc0[nt][3] + b2v * acc1[nt][3], 0.f) + e2.y,
                   xh[2 * nt + 1], xl[2 * nt + 1]);
        uint32_t h, l;
        split_pack(fmaxf(b1v * acc0[nt][0] + a1v * acc1[nt][0], 0.f) + d1.x,
                   fmaxf(b1v * acc0[nt][1] + a1v * acc1[nt][1], 0.f) + d1.y, h, l);
        scr[(2 * nt) * 32] = h;
        scr[(32 + 2 * nt) * 32] = l;
        split_pack(fmaxf(b2v * acc0[nt][2] + a2v * acc1[nt][2], 0.f) + d2.x,
                   fmaxf(b2v * acc0[nt][3] + a2v * acc1[nt][3], 0.f) + d2.y, h, l);
        scr[(2 * nt + 1) * 32] = h;
        scr[(32 + 2 * nt + 1) * 32] = l;
    }

    // score epilogue helper (per row rr): acc dot F / dot X; softmax; returns w0,w1
    auto softmax_row = [&](const float acc[16][4], const float* pF, int rr, bool x_in_regs,
                           float& w0, float& w1) {
        float s0 = 0.f, s1 = 0.f;
#pragma unroll
        for (int nt = 0; nt < 16; nt++) {
            int cc = 8 * nt + 2 * t;
            float2 e = *(const float2*)(pF + cc);
            float2 x = x_in_regs ? unpack2u(xh[2 * nt + rr], xl[2 * nt + rr])
                                 : unpack2u(scr[(2 * nt + rr) * 32], scr[(32 + 2 * nt + rr) * 32]);
            s0 += acc[nt][2 * rr] * e.x + acc[nt][2 * rr + 1] * e.y;
            s1 += acc[nt][2 * rr] * x.x + acc[nt][2 * rr + 1] * x.y;
        }
#pragma unroll
        for (int o = 1; o < 4; o <<= 1) {
            s0 += __shfl_xor_sync(~0u, s0, o);
            s1 += __shfl_xor_sync(~0u, s1, o);
        }
        float mx = fmaxf(s0, s1);
        float e0 = expf(s0 - mx), e1 = expf(s1 - mx);
        float inv = 1.f / (e0 + e1);
        w0 = e0 * inv;
        w1 = e1 * inv;
    };

    // ================= T_m (Mm in B) =================
    {
        float accT[16][4] = {};
        mbar_wait(fullB, 0);
        gemm_regA(xh, xl, WB, accT, g, t);
        if (lane == 0) MBAR_ARRIVE(freeB);
        float w01, w11, w02, w12;
        softmax_row(accT, pe1, 0, true, w01, w11);
        softmax_row(accT, pe2, 1, true, w02, w12);
#pragma unroll
        for (int nt = 0; nt < 16; nt++) {
            int cc = 8 * nt + 2 * t;
            float2 e1 = *(const float2*)(pe1 + cc), e2 = *(const float2*)(pe2 + cc);
            float2 x1 = unpack2u(xh[2 * nt], xl[2 * nt]);
            float2 x2 = unpack2u(xh[2 * nt + 1], xl[2 * nt + 1]);
            split_pack(w01 * e1.x + w11 * x1.x, w01 * e1.y + w11 * x1.y, xh[2 * nt], xl[2 * nt]);
            split_pack(w02 * e2.x + w12 * x2.x, w02 * e2.y + w12 * x2.y, xh[2 * nt + 1],
                       xl[2 * nt + 1]);
        }
    }
    // ================= T_d (Md in A, parity 1) =================
    {
        float accT[16][4] = {};
        mbar_wait(fullA, 1);
        gemm_smemA(scr, WA, accT, g, t);
        if (lane == 0) MBAR_ARRIVE(freeA);
        float w01, w11, w02, w12;
        softmax_row(accT, pd1, 0, false, w01, w11);
        softmax_row(accT, pd2, 1, false, w02, w12);
#pragma unroll
        for (int nt = 0; nt < 16; nt++) {
            int cc = 8 * nt + 2 * t;
            float2 d1 = *(const float2*)(pd1 + cc), d2 = *(const float2*)(pd2 + cc);
            float2 x1 = unpack2u(scr[(2 * nt) * 32], scr[(32 + 2 * nt) * 32]);
            float2 x2 = unpack2u(scr[(2 * nt + 1) * 32], scr[(32 + 2 * nt + 1) * 32]);
            uint32_t h, l;
            split_pack(w01 * d1.x + w11 * x1.x, w01 * d1.y + w11 * x1.y, h, l);
            scr[(2 * nt) * 32] = h;
            scr[(32 + 2 * nt) * 32] = l;
            split_pack(w02 * d2.x + w12 * x2.x, w02 * d2.y + w12 * x2.y, h, l);
            scr[(2 * nt + 1) * 32] = h;
            scr[(32 + 2 * nt + 1) * 32] = l;
        }
    }
    // ================= V_m (Wvm in B, parity 1) -> mla regs =================
    float mla[16][4] = {};
    mbar_wait(fullB, 1);
    gemm_regA(xh, xl, WB, mla, g, t);
    if (lane == 0) MBAR_ARRIVE(freeB);

    // ================= V_d (Wvd in A, parity 0) -> ne -> scratch =================
    {
        float dla[16][4] = {};
        mbar_wait(fullA, 0);
        gemm_smemA(scr, WA, dla, g, t);
#pragma unroll
        for (int nt = 0; nt < 16; nt++) {
            uint32_t h, l;
            split_pack(mla[nt][0] * dla[nt][0], mla[nt][1] * dla[nt][1], h, l);
            scr[(2 * nt) * 32] = h;
            scr[(32 + 2 * nt) * 32] = l;
            split_pack(mla[nt][2] * dla[nt][2], mla[nt][3] * dla[nt][3], h, l);
            scr[(2 * nt + 1) * 32] = h;
            scr[(32 + 2 * nt + 1) * 32] = l;
        }
    }
    // ================= head (W1 in B, parity 0) =================
    {
        float accH[16][4] = {};
        mbar_wait(fullB, 0);
        gemm_smemA(scr, WB, accH, g, t);
        float p1 = 0.f, p2 = 0.f;
#pragma unroll
        for (int nt = 0; nt < 16; nt++) {
            int cc = 8 * nt + 2 * t;
            float2 wv = *(const float2*)(W2 + cc);
            p1 += fmaxf(accH[nt][0], 0.f) * wv.x + fmaxf(accH[nt][1], 0.f) * wv.y;
            p2 += fmaxf(accH[nt][2], 0.f) * wv.x + fmaxf(accH[nt][3], 0.f) * wv.y;
        }
#pragma unroll
        for (int o = 1; o < 4; o <<= 1) {
            p1 += __shfl_xor_sync(~0u, p1, o);
            p2 += __shfl_xor_sync(~0u, p2, o);
        }
        if (t == 0) {
            out[row1] = 1.f / (1.f + expf(-p1));
            out[row2] = 1.f / (1.f + expf(-p2));
        }
    }
}

// ---------------------------------------------------------------------------
extern "C" void kernel_launch(void* const* d_in, const int* in_sizes, int n_in,
                              void* d_out, int out_size) {
    const float* em    = (const float*)d_in[0];
    const float* ed    = (const float*)d_in[1];
    const float* W_gcn = (const float*)d_in[2];
    const float* Wq_m  = (const float*)d_in[3];
    const float* Wk_m  = (const float*)d_in[4];
    const float* Wv_m  = (const float*)d_in[5];
    const float* Wq_d  = (const float*)d_in[6];
    const float* Wk_d  = (const float*)d_in[7];
    const float* Wv_d  = (const float*)d_in[8];
    const float* W1    = (const float*)d_in[9];
    const float* W2    = (const float*)d_in[10];
    float* out = (float*)d_out;

    const int B = in_sizes[0] / C;
    const int smem_bytes = U_TOT * 4;  // 204,864

    precompute_M_kernel<<<dim3(C, 2), C>>>(Wq_m, Wk_m, Wq_d, Wk_d);
    bake_kernel<<<dim3(8192 / 256, 6), 256>>>(W_gcn, Wv_m, Wv_d, W1);

    cudaFuncSetAttribute(fused_kernel,
                         cudaFuncAttributeMaxDynamicSharedMemorySize, smem_bytes);
    fused_kernel<<<B / 128, THREADS, smem_bytes>>>(em, ed, W2, out);
}

// round 16
// speedup vs baseline: 1.2130x; 1.2130x over previous
#include <cuda_runtime.h>
#include <cuda_bf16.h>
#include <cstdint>

#define C 128
#define LDW 132
#define WSTR 136
#define WPL (64 * WSTR)
#define THREADS 512
#define EPSF 1e-8f

__device__ float g_Mm[C * C];
__device__ float g_Md[C * C];
// bake order: 0 Wgcn, 1 Mm, 2 Wvm, 3 Md, 4 Wvd, 5 W1  (copy order uses 0,1,3,2,4,5)
__device__ __align__(16) uint32_t g_BH[6][WPL];
__device__ __align__(16) uint32_t g_BL[6][WPL];

// ---- smem u32 layout ----
#define U_R2 16
#define U_R3 (U_R2 + 8448)
#define U_WA (U_R3 + 8448)        // slot A: [WH | WL], 2*WPL
#define U_WB (U_WA + 2 * WPL)     // slot B
#define U_RED (U_WB + 2 * WPL)    // 4 x 256 floats
#define U_WS (U_RED + 1024)       // 4 x 64 floats: w0m,w1m,w0d,w1d
#define U_AB (U_WS + 256)
#define U_BB (U_AB + 64)
#define U_W2 (U_BB + 64)
#define U_TOT (U_W2 + 128)        // 53264 u32 = 213,056 B

__device__ __forceinline__ uint32_t s2u(const void* p) {
    uint32_t a;
    asm("{ .reg .u64 t; cvta.to.shared.u64 t, %1; cvt.u32.u64 %0, t; }" : "=r"(a) : "l"(p));
    return a;
}
#define MBAR_INIT(a, c) asm volatile("mbarrier.init.shared.b64 [%0], %1;" ::"r"(a), "r"(c) : "memory")
#define MBAR_EXPECT(a, b) \
    asm volatile("mbarrier.arrive.expect_tx.shared.b64 _, [%0], %1;" ::"r"(a), "r"(b) : "memory")
__device__ __forceinline__ void mbar_wait(uint32_t a, uint32_t par) {
    asm volatile(
        "{\n\t.reg .pred P;\n\tWL_%=:\n\t"
        "mbarrier.try_wait.parity.acquire.cta.shared::cta.b64 P, [%0], %1, 0x989680;\n\t"
        "@P bra.uni WD_%=;\n\tbra.uni WL_%=;\n\tWD_%=:\n\t}" ::"r"(a), "r"(par) : "memory");
}
__device__ __forceinline__ void bulk_g2s(uint32_t dst, const void* gsrc, uint32_t bytes,
                                         uint32_t mbar) {
    asm volatile(
        "{ .reg .u64 g; cvta.to.global.u64 g, %1;\n\t"
        "cp.async.bulk.shared::cluster.global.mbarrier::complete_tx::bytes [%0], [g], %2, [%3]; }"
        ::"r"(dst), "l"(gsrc), "r"(bytes), "r"(mbar) : "memory");
}

__device__ __forceinline__ void split_pack(float x0, float x1, uint32_t& h, uint32_t& l) {
    uint32_t u0 = __float_as_uint(x0), u1 = __float_as_uint(x1);
    h = __byte_perm(u0, u1, 0x7632);
    float l0 = x0 - __uint_as_float(u0 & 0xFFFF0000u);
    float l1 = x1 - __uint_as_float(u1 & 0xFFFF0000u);
    __nv_bfloat162 t = __floats2bfloat162_rn(l0, l1);
    l = *(uint32_t*)&t;
}
__device__ __forceinline__ uint2 pack2(float x, float y) {
    uint2 r;
    split_pack(x, y, r.x, r.y);
    return r;
}
__device__ __forceinline__ float2 unpack2(uint2 p) {
    float2 a = __bfloat1622float2(*(__nv_bfloat162*)&p.x);
    float2 b = __bfloat1622float2(*(__nv_bfloat162*)&p.y);
    return make_float2(a.x + b.x, a.y + b.y);
}
__device__ __forceinline__ void mma16816(float* d, const uint32_t* a, uint32_t b0, uint32_t b1) {
    asm volatile(
        "mma.sync.aligned.m16n8k16.row.col.f32.bf16.bf16.f32 "
        "{%0,%1,%2,%3}, {%4,%5,%6,%7}, {%8,%9}, {%0,%1,%2,%3};"
        : "+f"(d[0]), "+f"(d[1]), "+f"(d[2]), "+f"(d[3])
        : "r"(a[0]), "r"(a[1]), "r"(a[2]), "r"(a[3]), "r"(b0), "r"(b1));
}
#define MMA3(accn, bh0, bh1, bl0, bl1) \
    do {                               \
        mma16816(accn, ah, bh0, bh1);  \
        mma16816(accn, al, bh0, bh1);  \
        mma16816(accn, ah, bl0, bl1);  \
    } while (0)

// acc[nt][0..3]: rows (rb+g, rb+g+8), cols c32*32 + nt*8 + 2t (+1). W = slot base (WH | WL)
__device__ __forceinline__ void mma_block(const uint32_t* A, const uint32_t* W, float acc[4][4],
                                          int rb, int c32, int g, int t) {
    const uint32_t* pa = A + (rb + g) * LDW + 2 * t;
    const uint32_t* pb = W + t * WSTR + c32 * 32 + g * 4;
    const uint32_t* pc = pb + WPL;
#pragma unroll 2
    for (int k0 = 0; k0 < 8; k0++) {
        uint2 a0 = *(const uint2*)pa, a1 = *(const uint2*)(pa + 8 * LDW);
        uint2 a2 = *(const uint2*)(pa + 8), a3 = *(const uint2*)(pa + 8 * LDW + 8);
        uint4 bh0 = *(const uint4*)pb, bh1 = *(const uint4*)(pb + 4 * WSTR);
        uint4 bl0 = *(const uint4*)pc, bl1 = *(const uint4*)(pc + 4 * WSTR);
        uint32_t ah[4] = {a0.x, a1.x, a2.x, a3.x}, al[4] = {a0.y, a1.y, a2.y, a3.y};
        MMA3(acc[0], bh0.x, bh1.x, bl0.x, bl1.x);
        MMA3(acc[1], bh0.y, bh1.y, bl0.y, bl1.y);
        MMA3(acc[2], bh0.z, bh1.z, bl0.z, bl1.z);
        MMA3(acc[3], bh0.w, bh1.w, bl0.w, bl1.w);
        pa += 16;
        pb += 8 * WSTR;
        pc += 8 * WSTR;
    }
}
__device__ __forceinline__ void mma_block2(const uint32_t* A0, const uint32_t* A1,
                                           const uint32_t* W, float acc0[4][4], float acc1[4][4],
                                           int rb, int c32, int g, int t) {
    const uint32_t* pa = A0 + (rb + g) * LDW + 2 * t;
    const uint32_t* pq = A1 + (rb + g) * LDW + 2 * t;
    const uint32_t* pb = W + t * WSTR + c32 * 32 + g * 4;
    const uint32_t* pc = pb + WPL;
#pragma unroll 1
    for (int k0 = 0; k0 < 8; k0++) {
        uint4 bh0 = *(const uint4*)pb, bh1 = *(const uint4*)(pb + 4 * WSTR);
        uint4 bl0 = *(const uint4*)pc, bl1 = *(const uint4*)(pc + 4 * WSTR);
        {
            uint2 a0 = *(const uint2*)pa, a1 = *(const uint2*)(pa + 8 * LDW);
            uint2 a2 = *(const uint2*)(pa + 8), a3 = *(const uint2*)(pa + 8 * LDW + 8);
            uint32_t ah[4] = {a0.x, a1.x, a2.x, a3.x}, al[4] = {a0.y, a1.y, a2.y, a3.y};
            MMA3(acc0[0], bh0.x, bh1.x, bl0.x, bl1.x);
            MMA3(acc0[1], bh0.y, bh1.y, bl0.y, bl1.y);
            MMA3(acc0[2], bh0.z, bh1.z, bl0.z, bl1.z);
            MMA3(acc0[3], bh0.w, bh1.w, bl0.w, bl1.w);
        }
        {
            uint2 a0 = *(const uint2*)pq, a1 = *(const uint2*)(pq + 8 * LDW);
            uint2 a2 = *(const uint2*)(pq + 8), a3 = *(const uint2*)(pq + 8 * LDW + 8);
            uint32_t ah[4] = {a0.x, a1.x, a2.x, a3.x}, al[4] = {a0.y, a1.y, a2.y, a3.y};
            MMA3(acc1[0], bh0.x, bh1.x, bl0.x, bl1.x);
            MMA3(acc1[1], bh0.y, bh1.y, bl0.y, bl1.y);
            MMA3(acc1[2], bh0.z, bh1.z, bl0.z, bl1.z);
            MMA3(acc1[3], bh0.w, bh1.w, bl0.w, bl1.w);
        }
        pa += 16;
        pq += 16;
        pb += 8 * WSTR;
        pc += 8 * WSTR;
    }
}

// ---------------- prep ----------------
// one warp per output element: M[i][j] = (Wq[i] . Wk[j]) / sqrt(C)
// grid (1024, 2), block 256 (8 warps). 32768 warps per branch-pair -> fully parallel.
__global__ void precompute_M_kernel(const float* __restrict__ Wq_m, const float* __restrict__ Wk_m,
                                    const float* __restrict__ Wq_d, const float* __restrict__ Wk_d) {
    const float* Wq = blockIdx.y ? Wq_d : Wq_m;
    const float* Wk = blockIdx.y ? Wk_d : Wk_m;
    float* M = blockIdx.y ? g_Md : g_Mm;
    int wid = blockIdx.x * 8 + (threadIdx.x >> 5);  // 0..8191... need 16384
    int lane = threadIdx.x & 31;
    // each warp does TWO outputs (16384 total): out = wid and wid + 8192
#pragma unroll
    for (int rep = 0; rep < 2; rep++) {
        int o = wid + rep * 8192;
        int i = o >> 7, j = o & 127;
        const float* q = Wq + i * C;
        const float* k = Wk + j * C;
        float4 qa = *(const float4*)(q + 4 * lane);
        float4 ka = *(const float4*)(k + 4 * lane);
        float s = qa.x * ka.x + qa.y * ka.y + qa.z * ka.z + qa.w * ka.w;
#pragma unroll
        for (int off = 16; off; off >>= 1) s += __shfl_xor_sync(~0u, s, off);
        if (lane == 0) M[o] = s * 0.08838834764831845f;
    }
}

__global__ void bake_kernel(const float* __restrict__ Wg, const float* __restrict__ Wvm,
                            const float* __restrict__ Wvd, const float* __restrict__ W1) {
    int w = blockIdx.y;
    const float* src = (w == 0) ? Wg : (w == 1) ? g_Mm : (w == 2) ? Wvm
                      : (w == 3) ? g_Md : (w == 4) ? Wvd : W1;
    int idx = blockIdx.x * blockDim.x + threadIdx.x;  // 0..8191
    int nt = idx & 3, g = (idx >> 2) & 7, c32 = (idx >> 5) & 3, k2 = idx >> 7;
    int n = c32 * 32 + nt * 8 + g;
    uint32_t h, l;
    split_pack(src[(2 * k2) * C + n], src[(2 * k2 + 1) * C + n], h, l);
    int dst = k2 * WSTR + (idx & 127);
    g_BH[w][dst] = h;
    g_BL[w][dst] = l;
}

// ---------------- fused (identical to R13 best) ----------------
__global__ void __launch_bounds__(THREADS, 1)
fused_kernel(const float* __restrict__ em, const float* __restrict__ ed,
             const float* __restrict__ W2, float* __restrict__ out) {
    extern __shared__ uint32_t sm[];
    const uint32_t sb = s2u(sm);
    const uint32_t mbA = sb, mbB = sb + 8;
    uint32_t* R2 = sm + U_R2;
    uint32_t* R3 = sm + U_R3;
    uint32_t* WA = sm + U_WA;
    uint32_t* WB = sm + U_WB;
    float* red = (float*)(sm + U_RED);  // [4][256]
    float* wS = (float*)(sm + U_WS);    // [4][64]: w0m,w1m,w0d,w1d
    float* aB = (float*)(sm + U_AB);
    float* bB = (float*)(sm + U_BB);
    float* sW2 = (float*)(sm + U_W2);

    const int tid = threadIdx.x;
    const int w = tid >> 5, lane = tid & 31;
    const int g = lane >> 2, t = lane & 3;
    const int rb = (w & 3) * 16, c32 = w >> 2;
    const int r1 = rb + g, r2 = r1 + 8;
    const int cb = c32 * 32 + 2 * t;
    const int row4 = w * 4;
    const long base = (long)blockIdx.x * 64;

    auto copy_slot = [&](uint32_t mbar, uint32_t slot_u32, int wi) {
        MBAR_EXPECT(mbar, 2u * WPL * 4);
        bulk_g2s(sb + slot_u32 * 4, &g_BH[wi][0], WPL * 4, mbar);
        bulk_g2s(sb + (slot_u32 + WPL) * 4, &g_BL[wi][0], WPL * 4, mbar);
    };

    if (tid == 0) {
        MBAR_INIT(mbA, 1);
        MBAR_INIT(mbB, 1);
        copy_slot(mbA, U_WA, 0);  // Wgcn -> A
        copy_slot(mbB, U_WB, 1);  // Mm   -> B
    }
    if (tid < C) sW2[tid] = W2[tid];

    // adjacency scalars + pack em/ed from GLOBAL (warp owns rows row4..row4+3)
#pragma unroll
    for (int rr = 0; rr < 4; rr++) {
        int r = row4 + rr;
        const float* pe = em + (base + r) * C;
        const float* pd = ed + (base + r) * C;
        float2 e0 = *(const float2*)(pe + 2 * lane), e1 = *(const float2*)(pe + 2 * lane + 64);
        float2 d0 = *(const float2*)(pd + 2 * lane), d1 = *(const float2*)(pd + 2 * lane + 64);
        float sa = fabsf(e0.x - d0.x) + fabsf(e0.y - d0.y) + fabsf(e1.x - d1.x) + fabsf(e1.y - d1.y);
        float q0 = e0.x * e0.x + e0.y * e0.y + e1.x * e1.x + e1.y * e1.y;
        float q1 = d0.x * d0.x + d0.y * d0.y + d1.x * d1.x + d1.y * d1.y;
        float dp = e0.x * d0.x + e0.y * d0.y + e1.x * d1.x + e1.y * d1.y;
#pragma unroll
        for (int o = 16; o; o >>= 1) {
            sa += __shfl_xor_sync(~0u, sa, o);
            q0 += __shfl_xor_sync(~0u, q0, o);
            q1 += __shfl_xor_sync(~0u, q1, o);
            dp += __shfl_xor_sync(~0u, dp, o);
        }
        if (lane == 0) {
            float m = sa;
            float cosv = dp / (sqrtf(q0 + EPSF) * sqrtf(q1 + EPSF));
            float cp = cosv > 0.f ? cosv : 0.01f * cosv;
            aB[r] = fminf(1.f / (1.f + cp), 1.f / (1.f + m));
            bB[r] = fminf(cp / (1.f + cp), m / (1.f + m));
        }
        *(uint2*)(R2 + r * LDW + 2 * lane) = pack2(e0.x, e0.y);
        *(uint2*)(R2 + r * LDW + 2 * lane + 64) = pack2(e1.x, e1.y);
        *(uint2*)(R3 + r * LDW + 2 * lane) = pack2(d0.x, d0.y);
        *(uint2*)(R3 + r * LDW + 2 * lane + 64) = pack2(d1.x, d1.y);
    }
    __syncthreads();

    // ---------------- GCN (slot A: Wgcn) ----------------
    mbar_wait(mbA, 0);
    {
        float a0[4][4] = {}, a1[4][4] = {};
        mma_block2(R2, R3, WA, a0, a1, rb, c32, g, t);
        __syncthreads();
        if (tid == 0) copy_slot(mbA, U_WA, 3);  // Md -> A
        float aa1 = aB[r1], bb1 = bB[r1], aa2 = aB[r2], bb2 = bB[r2];
#pragma unroll
        for (int nt = 0; nt < 4; nt++) {
            int c = cb + nt * 8;
            float2 e1v = *(const float2*)(em + (base + r1) * C + c);
            float2 e2v = *(const float2*)(em + (base + r2) * C + c);
            float2 d1v = *(const float2*)(ed + (base + r1) * C + c);
            float2 d2v = *(const float2*)(ed + (base + r2) * C + c);
            *(uint2*)(R2 + r1 * LDW + c) = pack2(fmaxf(aa1 * a0[nt][0] + bb1 * a1[nt][0], 0.f) + e1v.x,
                                                 fmaxf(aa1 * a0[nt][1] + bb1 * a1[nt][1], 0.f) + e1v.y);
            *(uint2*)(R2 + r2 * LDW + c) = pack2(fmaxf(aa2 * a0[nt][2] + bb2 * a1[nt][2], 0.f) + e2v.x,
                                                 fmaxf(aa2 * a0[nt][3] + bb2 * a1[nt][3], 0.f) + e2v.y);
            *(uint2*)(R3 + r1 * LDW + c) = pack2(fmaxf(bb1 * a0[nt][0] + aa1 * a1[nt][0], 0.f) + d1v.x,
                                                 fmaxf(bb1 * a0[nt][1] + aa1 * a1[nt][1], 0.f) + d1v.y);
            *(uint2*)(R3 + r2 * LDW + c) = pack2(fmaxf(bb2 * a0[nt][2] + aa2 * a1[nt][2], 0.f) + d2v.x,
                                                 fmaxf(bb2 * a0[nt][3] + aa2 * a1[nt][3], 0.f) + d2v.y);
        }
    }
    __syncthreads();

    // ---------------- T stage: T_m (slot B: Mm), T_d (slot A: Md) ----------------
    float2 xAm[4], xBm[4], xAd[4], xBd[4];
    {
        float accm[4][4] = {}, accd[4][4] = {};
        mbar_wait(mbB, 0);
        mma_block(R2, WB, accm, rb, c32, g, t);
        mbar_wait(mbA, 1);
        mma_block(R3, WA, accd, rb, c32, g, t);
        __syncthreads();
        if (tid == 0) {
            copy_slot(mbB, U_WB, 2);  // Wvm -> B
            copy_slot(mbA, U_WA, 4);  // Wvd -> A
        }
        float s0a = 0.f, s1a = 0.f, s0b = 0.f, s1b = 0.f;
        float u0a = 0.f, u1a = 0.f, u0b = 0.f, u1b = 0.f;
#pragma unroll
        for (int nt = 0; nt < 4; nt++) {
            int c = cb + nt * 8;
            float2 f1 = *(const float2*)(em + (base + r1) * C + c);
            float2 f2 = *(const float2*)(em + (base + r2) * C + c);
            float2 h1 = *(const float2*)(ed + (base + r1) * C + c);
            float2 h2 = *(const float2*)(ed + (base + r2) * C + c);
            xAm[nt] = unpack2(*(const uint2*)(R2 + r1 * LDW + c));
            xBm[nt] = unpack2(*(const uint2*)(R2 + r2 * LDW + c));
            xAd[nt] = unpack2(*(const uint2*)(R3 + r1 * LDW + c));
            xBd[nt] = unpack2(*(const uint2*)(R3 + r2 * LDW + c));
            s0a += accm[nt][0] * f1.x + accm[nt][1] * f1.y;
            s1a += accm[nt][0] * xAm[nt].x + accm[nt][1] * xAm[nt].y;
            s0b += accm[nt][2] * f2.x + accm[nt][3] * f2.y;
            s1b += accm[nt][2] * xBm[nt].x + accm[nt][3] * xBm[nt].y;
            u0a += accd[nt][0] * h1.x + accd[nt][1] * h1.y;
            u1a += accd[nt][0] * xAd[nt].x + accd[nt][1] * xAd[nt].y;
            u0b += accd[nt][2] * h2.x + accd[nt][3] * h2.y;
            u1b += accd[nt][2] * xBd[nt].x + accd[nt][3] * xBd[nt].y;
        }
#pragma unroll
        for (int o = 1; o < 4; o <<= 1) {
            s0a += __shfl_xor_sync(~0u, s0a, o);
            s1a += __shfl_xor_sync(~0u, s1a, o);
            s0b += __shfl_xor_sync(~0u, s0b, o);
            s1b += __shfl_xor_sync(~0u, s1b, o);
            u0a += __shfl_xor_sync(~0u, u0a, o);
            u1a += __shfl_xor_sync(~0u, u1a, o);
            u0b += __shfl_xor_sync(~0u, u0b, o);
            u1b += __shfl_xor_sync(~0u, u1b, o);
        }
        if (t == 0) {
            red[0 * 256 + c32 * 64 + r1] = s0a;
            red[1 * 256 + c32 * 64 + r1] = s1a;
            red[0 * 256 + c32 * 64 + r2] = s0b;
            red[1 * 256 + c32 * 64 + r2] = s1b;
            red[2 * 256 + c32 * 64 + r1] = u0a;
            red[3 * 256 + c32 * 64 + r1] = u1a;
            red[2 * 256 + c32 * 64 + r2] = u0b;
            red[3 * 256 + c32 * 64 + r2] = u1b;
        }
    }
    __syncthreads();
    if (tid < 128) {
        int b = tid >> 6, r = tid & 63;
        const float* p0 = red + (2 * b) * 256 + r;
        const float* p1 = red + (2 * b + 1) * 256 + r;
        float S0 = p0[0] + p0[64] + p0[128] + p0[192];
        float S1 = p1[0] + p1[64] + p1[128] + p1[192];
        float mx = fmaxf(S0, S1);
        float e0 = expf(S0 - mx), e1 = expf(S1 - mx);
        float inv = 1.f / (e0 + e1);
        wS[(2 * b) * 64 + r] = e0 * inv;
        wS[(2 * b + 1) * 64 + r] = e1 * inv;
    }
    __syncthreads();
    {
        float w0m1 = wS[r1], w1m1 = wS[64 + r1], w0m2 = wS[r2], w1m2 = wS[64 + r2];
        float w0d1 = wS[128 + r1], w1d1 = wS[192 + r1], w0d2 = wS[128 + r2], w1d2 = wS[192 + r2];
#pragma unroll
        for (int nt = 0; nt < 4; nt++) {
            int c = cb + nt * 8;
            float2 f1 = *(const float2*)(em + (base + r1) * C + c);
            float2 f2 = *(const float2*)(em + (base + r2) * C + c);
            float2 h1 = *(const float2*)(ed + (base + r1) * C + c);
            float2 h2 = *(const float2*)(ed + (base + r2) * C + c);
            *(uint2*)(R2 + r1 * LDW + c) =
                pack2(w0m1 * f1.x + w1m1 * xAm[nt].x, w0m1 * f1.y + w1m1 * xAm[nt].y);
            *(uint2*)(R2 + r2 * LDW + c) =
                pack2(w0m2 * f2.x + w1m2 * xBm[nt].x, w0m2 * f2.y + w1m2 * xBm[nt].y);
            *(uint2*)(R3 + r1 * LDW + c) =
                pack2(w0d1 * h1.x + w1d1 * xAd[nt].x, w0d1 * h1.y + w1d1 * xAd[nt].y);
            *(uint2*)(R3 + r2 * LDW + c) =
                pack2(w0d2 * h2.x + w1d2 * xBd[nt].x, w0d2 * h2.y + w1d2 * xBd[nt].y);
        }
    }
    __syncthreads();

    // ---------------- V stage: mLA (slot B: Wvm), dLA (slot A: Wvd) ----------------
    {
        float mla[4][4] = {}, dla[4][4] = {};
        mbar_wait(mbB, 1);
        mma_block(R2, WB, mla, rb, c32, g, t);
        mbar_wait(mbA, 0);  // 3rd completion on A
        mma_block(R3, WA, dla, rb, c32, g, t);
        __syncthreads();
        if (tid == 0) copy_slot(mbB, U_WB, 5);  // W1 -> B
#pragma unroll
        for (int nt = 0; nt < 4; nt++) {
            int c = cb + nt * 8;
            *(uint2*)(R2 + r1 * LDW + c) = pack2(mla[nt][0] * dla[nt][0], mla[nt][1] * dla[nt][1]);
            *(uint2*)(R2 + r2 * LDW + c) = pack2(mla[nt][2] * dla[nt][2], mla[nt][3] * dla[nt][3]);
        }
    }
    __syncthreads();

    // ---------------- head (slot B: W1) ----------------
    mbar_wait(mbB, 0);  // 3rd completion on B
    {
        float acc[4][4] = {};
        mma_block(R2, WB, acc, rb, c32, g, t);
        float pa = 0.f, pb = 0.f;
#pragma unroll
        for (int nt = 0; nt < 4; nt++) {
            int c = cb + nt * 8;
            float2 wv = *(const float2*)(sW2 + c);
            pa += fmaxf(acc[nt][0], 0.f) * wv.x + fmaxf(acc[nt][1], 0.f) * wv.y;
            pb += fmaxf(acc[nt][2], 0.f) * wv.x + fmaxf(acc[nt][3], 0.f) * wv.y;
        }
#pragma unroll
        for (int o = 1; o < 4; o <<= 1) {
            pa += __shfl_xor_sync(~0u, pa, o);
            pb += __shfl_xor_sync(~0u, pb, o);
        }
        __syncthreads();
        if (t == 0) {
            red[c32 * 64 + r1] = pa;
            red[c32 * 64 + r2] = pb;
        }
        __syncthreads();
        if (tid < 64) {
            float P = red[tid] + red[64 + tid] + red[128 + tid] + red[192 + tid];
            out[base + tid] = 1.f / (1.f + expf(-P));
        }
    }
}

// ---------------------------------------------------------------------------
extern "C" void kernel_launch(void* const* d_in, const int* in_sizes, int n_in,
                              void* d_out, int out_size) {
    const float* em    = (const float*)d_in[0];
    const float* ed    = (const float*)d_in[1];
    const float* W_gcn = (const float*)d_in[2];
    const float* Wq_m  = (const float*)d_in[3];
    const float* Wk_m  = (const float*)d_in[4];
    const float* Wv_m  = (const float*)d_in[5];
    const float* Wq_d  = (const float*)d_in[6];
    const float* Wk_d  = (const float*)d_in[7];
    const float* Wv_d  = (const float*)d_in[8];
    const float* W1    = (const float*)d_in[9];
    const float* W2    = (const float*)d_in[10];
    float* out = (float*)d_out;

    const int B = in_sizes[0] / C;
    const int smem_bytes = U_TOT * 4;  // 213,056

    precompute_M_kernel<<<dim3(1024, 2), 256>>>(Wq_m, Wk_m, Wq_d, Wk_d);
    bake_kernel<<<dim3(8192 / 256, 6), 256>>>(W_gcn, Wv_m, Wv_d, W1);

    cudaFuncSetAttribute(fused_kernel,
                         cudaFuncAttributeMaxDynamicSharedMemorySize, smem_bytes);
    fused_kernel<<<B / 64, THREADS, smem_bytes>>>(em, ed, W2, out);
}

// round 17
// speedup vs baseline: 1.3268x; 1.0938x over previous
#include <cuda_runtime.h>
#include <cuda_bf16.h>
#include <cstdint>

#define C 128
#define LDW 132
#define WSTR 136
#define WPL (64 * WSTR)
#define THREADS 256
#define EPSF 1e-8f

__device__ float g_Mm[C * C];
__device__ float g_Md[C * C];
// bake order: 0 Wgcn, 1 Mm, 2 Wvm, 3 Md, 4 Wvd, 5 W1  (copy order: 0,1,3,2,4,5)
__device__ __align__(16) uint32_t g_BH[6][WPL];
__device__ __align__(16) uint32_t g_BL[6][WPL];

// ---- smem u32 layout (per CTA, 106,816 B -> 2 CTAs/SM) ----
#define U_R2 16
#define U_R3 (U_R2 + 32 * LDW)
#define U_WS (U_R3 + 32 * LDW)     // single weight slot [WH | WL]
#define U_RED (U_WS + 2 * WPL)     // 4 x 128 floats
#define U_WSM (U_RED + 512)        // 4 x 32 floats
#define U_AB (U_WSM + 128)         // aB[32], bB[32]
#define U_W2 (U_AB + 64)
#define U_TOT (U_W2 + 128)         // 26704 u32 = 106,816 B

__device__ __forceinline__ uint32_t s2u(const void* p) {
    uint32_t a;
    asm("{ .reg .u64 t; cvta.to.shared.u64 t, %1; cvt.u32.u64 %0, t; }" : "=r"(a) : "l"(p));
    return a;
}
#define MBAR_INIT(a, c) asm volatile("mbarrier.init.shared.b64 [%0], %1;" ::"r"(a), "r"(c) : "memory")
#define MBAR_EXPECT(a, b) \
    asm volatile("mbarrier.arrive.expect_tx.shared.b64 _, [%0], %1;" ::"r"(a), "r"(b) : "memory")
__device__ __forceinline__ void mbar_wait(uint32_t a, uint32_t par) {
    asm volatile(
        "{\n\t.reg .pred P;\n\tWL_%=:\n\t"
        "mbarrier.try_wait.parity.acquire.cta.shared::cta.b64 P, [%0], %1, 0x989680;\n\t"
        "@P bra.uni WD_%=;\n\tbra.uni WL_%=;\n\tWD_%=:\n\t}" ::"r"(a), "r"(par) : "memory");
}
__device__ __forceinline__ void bulk_g2s(uint32_t dst, const void* gsrc, uint32_t bytes,
                                         uint32_t mbar) {
    asm volatile(
        "{ .reg .u64 g; cvta.to.global.u64 g, %1;\n\t"
        "cp.async.bulk.shared::cluster.global.mbarrier::complete_tx::bytes [%0], [g], %2, [%3]; }"
        ::"r"(dst), "l"(gsrc), "r"(bytes), "r"(mbar) : "memory");
}

__device__ __forceinline__ void split_pack(float x0, float x1, uint32_t& h, uint32_t& l) {
    uint32_t u0 = __float_as_uint(x0), u1 = __float_as_uint(x1);
    h = __byte_perm(u0, u1, 0x7632);
    float l0 = x0 - __uint_as_float(u0 & 0xFFFF0000u);
    float l1 = x1 - __uint_as_float(u1 & 0xFFFF0000u);
    __nv_bfloat162 t = __floats2bfloat162_rn(l0, l1);
    l = *(uint32_t*)&t;
}
__device__ __forceinline__ uint2 pack2(float x, float y) {
    uint2 r;
    split_pack(x, y, r.x, r.y);
    return r;
}
__device__ __forceinline__ float2 unpack2(uint2 p) {
    float2 a = __bfloat1622float2(*(__nv_bfloat162*)&p.x);
    float2 b = __bfloat1622float2(*(__nv_bfloat162*)&p.y);
    return make_float2(a.x + b.x, a.y + b.y);
}
__device__ __forceinline__ void mma16816(float* d, const uint32_t* a, uint32_t b0, uint32_t b1) {
    asm volatile(
        "mma.sync.aligned.m16n8k16.row.col.f32.bf16.bf16.f32 "
        "{%0,%1,%2,%3}, {%4,%5,%6,%7}, {%8,%9}, {%0,%1,%2,%3};"
        : "+f"(d[0]), "+f"(d[1]), "+f"(d[2]), "+f"(d[3])
        : "r"(a[0]), "r"(a[1]), "r"(a[2]), "r"(a[3]), "r"(b0), "r"(b1));
}
#define MMA3(accn, bh0, bh1, bl0, bl1) \
    do {                               \
        mma16816(accn, ah, bh0, bh1);  \
        mma16816(accn, al, bh0, bh1);  \
        mma16816(accn, ah, bl0, bl1);  \
    } while (0)

// acc[nt][0..3]: rows (rb+g, rb+g+8), cols c32*32 + nt*8 + 2t (+1)
__device__ __forceinline__ void mma_block(const uint32_t* A, const uint32_t* W, float acc[4][4],
                                          int rb, int c32, int g, int t) {
    const uint32_t* pa = A + (rb + g) * LDW + 2 * t;
    const uint32_t* pb = W + t * WSTR + c32 * 32 + g * 4;
    const uint32_t* pc = pb + WPL;
#pragma unroll 2
    for (int k0 = 0; k0 < 8; k0++) {
        uint2 a0 = *(const uint2*)pa, a1 = *(const uint2*)(pa + 8 * LDW);
        uint2 a2 = *(const uint2*)(pa + 8), a3 = *(const uint2*)(pa + 8 * LDW + 8);
        uint4 bh0 = *(const uint4*)pb, bh1 = *(const uint4*)(pb + 4 * WSTR);
        uint4 bl0 = *(const uint4*)pc, bl1 = *(const uint4*)(pc + 4 * WSTR);
        uint32_t ah[4] = {a0.x, a1.x, a2.x, a3.x}, al[4] = {a0.y, a1.y, a2.y, a3.y};
        MMA3(acc[0], bh0.x, bh1.x, bl0.x, bl1.x);
        MMA3(acc[1], bh0.y, bh1.y, bl0.y, bl1.y);
        MMA3(acc[2], bh0.z, bh1.z, bl0.z, bl1.z);
        MMA3(acc[3], bh0.w, bh1.w, bl0.w, bl1.w);
        pa += 16;
        pb += 8 * WSTR;
        pc += 8 * WSTR;
    }
}
__device__ __forceinline__ void mma_block2(const uint32_t* A0, const uint32_t* A1,
                                           const uint32_t* W, float acc0[4][4], float acc1[4][4],
                                           int rb, int c32, int g, int t) {
    const uint32_t* pa = A0 + (rb + g) * LDW + 2 * t;
    const uint32_t* pq = A1 + (rb + g) * LDW + 2 * t;
    const uint32_t* pb = W + t * WSTR + c32 * 32 + g * 4;
    const uint32_t* pc = pb + WPL;
#pragma unroll 1
    for (int k0 = 0; k0 < 8; k0++) {
        uint4 bh0 = *(const uint4*)pb, bh1 = *(const uint4*)(pb + 4 * WSTR);
        uint4 bl0 = *(const uint4*)pc, bl1 = *(const uint4*)(pc + 4 * WSTR);
        {
            uint2 a0 = *(const uint2*)pa, a1 = *(const uint2*)(pa + 8 * LDW);
            uint2 a2 = *(const uint2*)(pa + 8), a3 = *(const uint2*)(pa + 8 * LDW + 8);
            uint32_t ah[4] = {a0.x, a1.x, a2.x, a3.x}, al[4] = {a0.y, a1.y, a2.y, a3.y};
            MMA3(acc0[0], bh0.x, bh1.x, bl0.x, bl1.x);
            MMA3(acc0[1], bh0.y, bh1.y, bl0.y, bl1.y);
            MMA3(acc0[2], bh0.z, bh1.z, bl0.z, bl1.z);
            MMA3(acc0[3], bh0.w, bh1.w, bl0.w, bl1.w);
        }
        {
            uint2 a0 = *(const uint2*)pq, a1 = *(const uint2*)(pq + 8 * LDW);
            uint2 a2 = *(const uint2*)(pq + 8), a3 = *(const uint2*)(pq + 8 * LDW + 8);
            uint32_t ah[4] = {a0.x, a1.x, a2.x, a3.x}, al[4] = {a0.y, a1.y, a2.y, a3.y};
            MMA3(acc1[0], bh0.x, bh1.x, bl0.x, bl1.x);
            MMA3(acc1[1], bh0.y, bh1.y, bl0.y, bl1.y);
            MMA3(acc1[2], bh0.z, bh1.z, bl0.z, bl1.z);
            MMA3(acc1[3], bh0.w, bh1.w, bl0.w, bl1.w);
        }
        pa += 16;
        pq += 16;
        pb += 8 * WSTR;
        pc += 8 * WSTR;
    }
}

// ---------------- prep ----------------
__global__ void precompute_M_kernel(const float* __restrict__ Wq_m, const float* __restrict__ Wk_m,
                                    const float* __restrict__ Wq_d, const float* __restrict__ Wk_d) {
    const float* Wq = blockIdx.y ? Wq_d : Wq_m;
    const float* Wk = blockIdx.y ? Wk_d : Wk_m;
    float* M = blockIdx.y ? g_Md : g_Mm;
    int wid = blockIdx.x * 8 + (threadIdx.x >> 5);
    int lane = threadIdx.x & 31;
#pragma unroll
    for (int rep = 0; rep < 2; rep++) {
        int o = wid + rep * 8192;
        int i = o >> 7, j = o & 127;
        float4 qa = *(const float4*)(Wq + i * C + 4 * lane);
        float4 ka = *(const float4*)(Wk + j * C + 4 * lane);
        float s = qa.x * ka.x + qa.y * ka.y + qa.z * ka.z + qa.w * ka.w;
#pragma unroll
        for (int off = 16; off; off >>= 1) s += __shfl_xor_sync(~0u, s, off);
        if (lane == 0) M[o] = s * 0.08838834764831845f;
    }
}

__global__ void bake_kernel(const float* __restrict__ Wg, const float* __restrict__ Wvm,
                            const float* __restrict__ Wvd, const float* __restrict__ W1) {
    int w = blockIdx.y;
    const float* src = (w == 0) ? Wg : (w == 1) ? g_Mm : (w == 2) ? Wvm
                      : (w == 3) ? g_Md : (w == 4) ? Wvd : W1;
    int idx = blockIdx.x * blockDim.x + threadIdx.x;
    int nt = idx & 3, g = (idx >> 2) & 7, c32 = (idx >> 5) & 3, k2 = idx >> 7;
    int n = c32 * 32 + nt * 8 + g;
    uint32_t h, l;
    split_pack(src[(2 * k2) * C + n], src[(2 * k2 + 1) * C + n], h, l);
    g_BH[w][k2 * WSTR + (idx & 127)] = h;
    g_BL[w][k2 * WSTR + (idx & 127)] = l;
}

// ---------------- fused: 32 rows/CTA, 2 CTAs/SM ----------------
__global__ void __launch_bounds__(THREADS, 2)
fused_kernel(const float* __restrict__ em, const float* __restrict__ ed,
             const float* __restrict__ W2, float* __restrict__ out) {
    extern __shared__ uint32_t sm[];
    const uint32_t sb = s2u(sm);
    const uint32_t mb = sb;
    uint32_t* R2 = sm + U_R2;
    uint32_t* R3 = sm + U_R3;
    uint32_t* WS = sm + U_WS;
    float* red = (float*)(sm + U_RED);  // [4][128]: (c32, row)
    float* wS = (float*)(sm + U_WSM);   // [4][32]: w0m,w1m,w0d,w1d
    float* aB = (float*)(sm + U_AB);    // [32]
    float* bB = aB + 32;
    float* sW2 = (float*)(sm + U_W2);

    const int tid = threadIdx.x;
    const int w = tid >> 5, lane = tid & 31;
    const int g = lane >> 2, t = lane & 3;
    const int rb = (w & 1) * 16, c32 = w >> 1;
    const int r1 = rb + g, r2 = r1 + 8;
    const int cb = c32 * 32 + 2 * t;
    const int row4 = w * 4;
    const long base = (long)blockIdx.x * 32;

    auto copy_w = [&](int wi) {
        if (tid == 0) {
            MBAR_EXPECT(mb, 2u * WPL * 4);
            bulk_g2s(sb + U_WS * 4, &g_BH[wi][0], WPL * 4, mb);
            bulk_g2s(sb + (U_WS + WPL) * 4, &g_BL[wi][0], WPL * 4, mb);
        }
    };

    if (tid == 0) {
        MBAR_INIT(mb, 1);
        MBAR_EXPECT(mb, 2u * WPL * 4);
        bulk_g2s(sb + U_WS * 4, &g_BH[0][0], WPL * 4, mb);            // Wgcn (p0)
        bulk_g2s(sb + (U_WS + WPL) * 4, &g_BL[0][0], WPL * 4, mb);
    }
    if (tid < C) sW2[tid] = W2[tid];

    // adjacency + pack em/ed (warp owns rows row4..row4+3 of 32)
#pragma unroll
    for (int rr = 0; rr < 4; rr++) {
        int r = row4 + rr;
        const float* pe = em + (base + r) * C;
        const float* pd = ed + (base + r) * C;
        float2 e0 = *(const float2*)(pe + 2 * lane), e1 = *(const float2*)(pe + 2 * lane + 64);
        float2 d0 = *(const float2*)(pd + 2 * lane), d1 = *(const float2*)(pd + 2 * lane + 64);
        float sa = fabsf(e0.x - d0.x) + fabsf(e0.y - d0.y) + fabsf(e1.x - d1.x) + fabsf(e1.y - d1.y);
        float q0 = e0.x * e0.x + e0.y * e0.y + e1.x * e1.x + e1.y * e1.y;
        float q1 = d0.x * d0.x + d0.y * d0.y + d1.x * d1.x + d1.y * d1.y;
        float dp = e0.x * d0.x + e0.y * d0.y + e1.x * d1.x + e1.y * d1.y;
#pragma unroll
        for (int o = 16; o; o >>= 1) {
            sa += __shfl_xor_sync(~0u, sa, o);
            q0 += __shfl_xor_sync(~0u, q0, o);
            q1 += __shfl_xor_sync(~0u, q1, o);
            dp += __shfl_xor_sync(~0u, dp, o);
        }
        if (lane == 0) {
            float m = sa;
            float cosv = dp / (sqrtf(q0 + EPSF) * sqrtf(q1 + EPSF));
            float cp = cosv > 0.f ? cosv : 0.01f * cosv;
            aB[r] = fminf(1.f / (1.f + cp), 1.f / (1.f + m));
            bB[r] = fminf(cp / (1.f + cp), m / (1.f + m));
        }
        *(uint2*)(R2 + r * LDW + 2 * lane) = pack2(e0.x, e0.y);
        *(uint2*)(R2 + r * LDW + 2 * lane + 64) = pack2(e1.x, e1.y);
        *(uint2*)(R3 + r * LDW + 2 * lane) = pack2(d0.x, d0.y);
        *(uint2*)(R3 + r * LDW + 2 * lane + 64) = pack2(d1.x, d1.y);
    }
    __syncthreads();

    // ---------------- GCN (Wgcn, p0) ----------------
    mbar_wait(mb, 0);
    {
        float a0[4][4] = {}, a1[4][4] = {};
        mma_block2(R2, R3, WS, a0, a1, rb, c32, g, t);
        __syncthreads();
        copy_w(1);  // Mm -> p1
        float aa1 = aB[r1], bb1 = bB[r1], aa2 = aB[r2], bb2 = bB[r2];
#pragma unroll
        for (int nt = 0; nt < 4; nt++) {
            int c = cb + nt * 8;
            float2 e1v = *(const float2*)(em + (base + r1) * C + c);
            float2 e2v = *(const float2*)(em + (base + r2) * C + c);
            float2 d1v = *(const float2*)(ed + (base + r1) * C + c);
            float2 d2v = *(const float2*)(ed + (base + r2) * C + c);
            *(uint2*)(R2 + r1 * LDW + c) = pack2(fmaxf(aa1 * a0[nt][0] + bb1 * a1[nt][0], 0.f) + e1v.x,
                                                 fmaxf(aa1 * a0[nt][1] + bb1 * a1[nt][1], 0.f) + e1v.y);
            *(uint2*)(R2 + r2 * LDW + c) = pack2(fmaxf(aa2 * a0[nt][2] + bb2 * a1[nt][2], 0.f) + e2v.x,
                                                 fmaxf(aa2 * a0[nt][3] + bb2 * a1[nt][3], 0.f) + e2v.y);
            *(uint2*)(R3 + r1 * LDW + c) = pack2(fmaxf(bb1 * a0[nt][0] + aa1 * a1[nt][0], 0.f) + d1v.x,
                                                 fmaxf(bb1 * a0[nt][1] + aa1 * a1[nt][1], 0.f) + d1v.y);
            *(uint2*)(R3 + r2 * LDW + c) = pack2(fmaxf(bb2 * a0[nt][2] + aa2 * a1[nt][2], 0.f) + d2v.x,
                                                 fmaxf(bb2 * a0[nt][3] + aa2 * a1[nt][3], 0.f) + d2v.y);
        }
    }
    __syncthreads();

    float2 xAm[4], xBm[4], xAd[4], xBd[4];
    // fold helper: scores for one branch into red slots (s0s, s1s), retain x in regs
    auto fold = [&](const float acc[4][4], const uint32_t* X, const float* F, float2* xA,
                    float2* xB, int s0s, int s1s) {
        float s0a = 0.f, s1a = 0.f, s0b = 0.f, s1b = 0.f;
#pragma unroll
        for (int nt = 0; nt < 4; nt++) {
            int c = cb + nt * 8;
            float2 f1 = *(const float2*)(F + (base + r1) * C + c);
            float2 f2 = *(const float2*)(F + (base + r2) * C + c);
            xA[nt] = unpack2(*(const uint2*)(X + r1 * LDW + c));
            xB[nt] = unpack2(*(const uint2*)(X + r2 * LDW + c));
            s0a += acc[nt][0] * f1.x + acc[nt][1] * f1.y;
            s1a += acc[nt][0] * xA[nt].x + acc[nt][1] * xA[nt].y;
            s0b += acc[nt][2] * f2.x + acc[nt][3] * f2.y;
            s1b += acc[nt][2] * xB[nt].x + acc[nt][3] * xB[nt].y;
        }
#pragma unroll
        for (int o = 1; o < 4; o <<= 1) {
            s0a += __shfl_xor_sync(~0u, s0a, o);
            s1a += __shfl_xor_sync(~0u, s1a, o);
            s0b += __shfl_xor_sync(~0u, s0b, o);
            s1b += __shfl_xor_sync(~0u, s1b, o);
        }
        if (t == 0) {
            red[s0s * 128 + c32 * 32 + r1] = s0a;
            red[s1s * 128 + c32 * 32 + r1] = s1a;
            red[s0s * 128 + c32 * 32 + r2] = s0b;
            red[s1s * 128 + c32 * 32 + r2] = s1b;
        }
    };

    // ---------------- T_m (Mm, p1) ----------------
    {
        float accm[4][4] = {};
        mbar_wait(mb, 1);
        mma_block(R2, WS, accm, rb, c32, g, t);
        __syncthreads();
        copy_w(3);  // Md -> p0
        fold(accm, R2, em, xAm, xBm, 0, 1);
    }
    // ---------------- T_d (Md, p0) ----------------
    {
        float accd[4][4] = {};
        mbar_wait(mb, 0);
        mma_block(R3, WS, accd, rb, c32, g, t);
        __syncthreads();
        copy_w(2);  // Wvm -> p1
        fold(accd, R3, ed, xAd, xBd, 2, 3);
    }
    __syncthreads();
    if (tid < 64) {  // softmax both branches: b = tid>>5, r = tid&31
        int b = tid >> 5, r = tid & 31;
        const float* p0 = red + (2 * b) * 128 + r;
        const float* p1 = red + (2 * b + 1) * 128 + r;
        float S0 = p0[0] + p0[32] + p0[64] + p0[96];
        float S1 = p1[0] + p1[32] + p1[64] + p1[96];
        float mx = fmaxf(S0, S1);
        float e0 = expf(S0 - mx), e1 = expf(S1 - mx);
        float inv = 1.f / (e0 + e1);
        wS[(2 * b) * 32 + r] = e0 * inv;
        wS[(2 * b + 1) * 32 + r] = e1 * inv;
    }
    __syncthreads();
    {  // u-pack both branches
        float w0m1 = wS[r1], w1m1 = wS[32 + r1], w0m2 = wS[r2], w1m2 = wS[32 + r2];
        float w0d1 = wS[64 + r1], w1d1 = wS[96 + r1], w0d2 = wS[64 + r2], w1d2 = wS[96 + r2];
#pragma unroll
        for (int nt = 0; nt < 4; nt++) {
            int c = cb + nt * 8;
            float2 f1 = *(const float2*)(em + (base + r1) * C + c);
            float2 f2 = *(const float2*)(em + (base + r2) * C + c);
            float2 h1 = *(const float2*)(ed + (base + r1) * C + c);
            float2 h2 = *(const float2*)(ed + (base + r2) * C + c);
            *(uint2*)(R2 + r1 * LDW + c) =
                pack2(w0m1 * f1.x + w1m1 * xAm[nt].x, w0m1 * f1.y + w1m1 * xAm[nt].y);
            *(uint2*)(R2 + r2 * LDW + c) =
                pack2(w0m2 * f2.x + w1m2 * xBm[nt].x, w0m2 * f2.y + w1m2 * xBm[nt].y);
            *(uint2*)(R3 + r1 * LDW + c) =
                pack2(w0d1 * h1.x + w1d1 * xAd[nt].x, w0d1 * h1.y + w1d1 * xAd[nt].y);
            *(uint2*)(R3 + r2 * LDW + c) =
                pack2(w0d2 * h2.x + w1d2 * xBd[nt].x, w0d2 * h2.y + w1d2 * xBd[nt].y);
        }
    }
    __syncthreads();

    // ---------------- V_m (Wvm, p1) ----------------
    float mla[4][4] = {};
    mbar_wait(mb, 1);
    mma_block(R2, WS, mla, rb, c32, g, t);
    __syncthreads();
    copy_w(4);  // Wvd -> p0

    // ---------------- V_d (Wvd, p0) + ne ----------------
    {
        float dla[4][4] = {};
        mbar_wait(mb, 0);
        mma_block(R3, WS, dla, rb, c32, g, t);
#pragma unroll
        for (int nt = 0; nt < 4; nt++) {
            int c = cb + nt * 8;
            *(uint2*)(R2 + r1 * LDW + c) = pack2(mla[nt][0] * dla[nt][0], mla[nt][1] * dla[nt][1]);
            *(uint2*)(R2 + r2 * LDW + c) = pack2(mla[nt][2] * dla[nt][2], mla[nt][3] * dla[nt][3]);
        }
    }
    __syncthreads();
    copy_w(5);  // W1 -> p1

    // ---------------- head (W1, p1) ----------------
    mbar_wait(mb, 1);
    {
        float acc[4][4] = {};
        mma_block(R2, WS, acc, rb, c32, g, t);
        float pa = 0.f, pb = 0.f;
#pragma unroll
        for (int nt = 0; nt < 4; nt++) {
            int c = cb + nt * 8;
            float2 wv = *(const float2*)(sW2 + c);
            pa += fmaxf(acc[nt][0], 0.f) * wv.x + fmaxf(acc[nt][1], 0.f) * wv.y;
            pb += fmaxf(acc[nt][2], 0.f) * wv.x + fmaxf(acc[nt][3], 0.f) * wv.y;
        }
#pragma unroll
        for (int o = 1; o < 4; o <<= 1) {
            pa += __shfl_xor_sync(~0u, pa, o);
            pb += __shfl_xor_sync(~0u, pb, o);
        }
        __syncthreads();
        if (t == 0) {
            red[c32 * 32 + r1] = pa;
            red[c32 * 32 + r2] = pb;
        }
        __syncthreads();
        if (tid < 32) {
            float P = red[tid] + red[32 + tid] + red[64 + tid] + red[96 + tid];
            out[base + tid] = 1.f / (1.f + expf(-P));
        }
    }
}

// ---------------------------------------------------------------------------
extern "C" void kernel_launch(void* const* d_in, const int* in_sizes, int n_in,
                              void* d_out, int out_size) {
    const float* em    = (const float*)d_in[0];
    const float* ed    = (const float*)d_in[1];
    const float* W_gcn = (const float*)d_in[2];
    const float* Wq_m  = (const float*)d_in[3];
    const float* Wk_m  = (const float*)d_in[4];
    const float* Wv_m  = (const float*)d_in[5];
    const float* Wq_d  = (const float*)d_in[6];
    const float* Wk_d  = (const float*)d_in[7];
    const float* Wv_d  = (const float*)d_in[8];
    const float* W1    = (const float*)d_in[9];
    const float* W2    = (const float*)d_in[10];
    float* out = (float*)d_out;

    const int B = in_sizes[0] / C;
    const int smem_bytes = U_TOT * 4;  // 106,816

    precompute_M_kernel<<<dim3(1024, 2), 256>>>(Wq_m, Wk_m, Wq_d, Wk_d);
    bake_kernel<<<dim3(8192 / 256, 6), 256>>>(W_gcn, Wv_m, Wv_d, W1);

    cudaFuncSetAttribute(fused_kernel,
                         cudaFuncAttributeMaxDynamicSharedMemorySize, smem_bytes);
    fused_kernel<<<B / 32, THREADS, smem_bytes>>>(em, ed, W2, out);
}